// round 5
// baseline (speedup 1.0000x reference)
#include <cuda_runtime.h>
#include <cstdint>

// ============================================================================
// SequenceMemoryUpdater v4 — mma.sync tf32 + bulk-copy staging + overlapped copy
//
//   main stream: zero_mask -> set_mask -> lu_copy -> [fork] -> gru -> [join]
//   side stream:                         [fork] -> masked copy_mem -> [join]
//
// GRU kernel (per 64-row tile):
//   gates[b,0:512]: 0..127 r, 128..255 z, 256..383 i_n (x-K), 384..511 h_n (h-K)
//   12 K-chunks of 32. Chunk staging = 448 x 128B cp.async.bulk (warp 0 only)
//   into a 3-slot ring, completion via mbarrier expect_tx. mma.sync tf32 with
//   raw-fp32 operands (HW truncation). Register-resident GRU epilogue.
// ============================================================================

#define BLOCK_M   64
#define THREADS   512

// smem byte offsets
#define OFF_MBAR   0            // 3 mbarriers (8B each)
#define OFF_BIAS   64           // 512 floats
#define OFF_IDS    2112         // 64 ints
#define OFF_SLOT0  2432         // 3 slots x 64512B; slot: W 384x36f, A 64x36f
#define SLOT_BYTES 64512
#define SLOT_A_OFF 55296        // A tile starts after 384*144B of W
#define SMEM_BYTES (OFF_SLOT0 + 3 * SLOT_BYTES)   // 195968

#define MASK_WORDS 32768        // 1M nodes / 32
__device__ uint32_t g_mask[MASK_WORDS];

// ---- PTX helpers (all sm_90-base legal) ----
#define MBAR_INIT(addr, cnt) \
    asm volatile("mbarrier.init.shared.b64 [%0], %1;" :: "r"(addr), "r"(cnt) : "memory")
#define MBAR_EXPECT_TX(addr, bytes) \
    asm volatile("mbarrier.arrive.expect_tx.shared.b64 _, [%0], %1;" \
                 :: "r"(addr), "r"(bytes) : "memory")
#define FENCE_ASYNC() asm volatile("fence.proxy.async.shared::cta;" ::: "memory")

__device__ __forceinline__ void mbar_wait(uint32_t addr, uint32_t parity) {
    asm volatile(
        "{\n\t.reg .pred P;\n"
        "W_%=:\n\t"
        "mbarrier.try_wait.parity.acquire.cta.shared::cta.b64 P, [%0], %1, 0x989680;\n\t"
        "@P bra.uni D_%=;\n\t"
        "bra.uni W_%=;\n"
        "D_%=:\n\t}"
        :: "r"(addr), "r"(parity) : "memory");
}

__device__ __forceinline__ void bulk_cp128(uint32_t dst_smem, const void* src,
                                           uint32_t mbar) {
    asm volatile(
        "cp.async.bulk.shared::cluster.global.mbarrier::complete_tx::bytes "
        "[%0], [%1], 128, [%2];"
        :: "r"(dst_smem), "l"(src), "r"(mbar) : "memory");
}

// raw fp32 bits fed as tf32 (HW truncates low 13 mantissa bits)
__device__ __forceinline__ void mma_tf32(float* d, const float* a,
                                         float b0, float b1) {
    asm volatile(
        "mma.sync.aligned.m16n8k8.row.col.f32.tf32.tf32.f32 "
        "{%0,%1,%2,%3}, {%4,%5,%6,%7}, {%8,%9}, {%0,%1,%2,%3};"
        : "+f"(d[0]), "+f"(d[1]), "+f"(d[2]), "+f"(d[3])
        : "r"(__float_as_uint(a[0])), "r"(__float_as_uint(a[1])),
          "r"(__float_as_uint(a[2])), "r"(__float_as_uint(a[3])),
          "r"(__float_as_uint(b0)),  "r"(__float_as_uint(b1)));
}

__device__ __forceinline__ float gru_one(float pr, float pz, float pin,
                                         float phn, float h) {
    float r = 1.0f / (1.0f + __expf(-pr));
    float z = 1.0f / (1.0f + __expf(-pz));
    float n = tanhf(fmaf(r, phn, pin));
    return fmaf(z, h - n, n);   // (1-z)*n + z*h
}

// ---------------------------------------------------------------------------
// mask kernels
// ---------------------------------------------------------------------------
__global__ void zero_mask_kernel(int n_words) {
    int i = blockIdx.x * blockDim.x + threadIdx.x;
    if (i < n_words) g_mask[i] = 0u;
}
__global__ void set_mask_kernel(const int* __restrict__ ids, int B) {
    int i = blockIdx.x * blockDim.x + threadIdx.x;
    if (i < B) {
        int node = ids[i];
        atomicOr(&g_mask[node >> 5], 1u << (node & 31));
    }
}

// ---------------------------------------------------------------------------
// copies
// ---------------------------------------------------------------------------
__global__ void lu_copy_kernel(const float4* __restrict__ lu,
                               float4* __restrict__ out, int n4) {
    int i = blockIdx.x * blockDim.x + threadIdx.x;
    if (i < n4) out[i] = lu[i];
}

// one warp == one 128-float row; skip rows GRU will write
__global__ void copy_mem_kernel(const float4* __restrict__ mem,
                                float4* __restrict__ out, int n_rows) {
    int idx = blockIdx.x * blockDim.x + threadIdx.x;   // float4 index
    int row = idx >> 5;
    if (row >= n_rows) return;
    if ((g_mask[row >> 5] >> (row & 31)) & 1u) return;
    out[idx] = mem[idx];
}

// ---------------------------------------------------------------------------
// stage chunk kc into ring slot kc%3 via cp.async.bulk (called by warp 0 only)
// 448 rows of 128B: rows 0..383 = W chunk, rows 384..447 = A chunk
// ---------------------------------------------------------------------------
__device__ __forceinline__ void stage_bulk(uint32_t smb, int kc,
                                           const float* __restrict__ messages,
                                           const float* __restrict__ memory,
                                           const int* __restrict__ ids_s,
                                           const float* __restrict__ W_ih,
                                           const float* __restrict__ W_hh,
                                           int row0, int B, int lane) {
    const int slot = kc % 3;
    const uint32_t mbar = smb + OFF_MBAR + 8 * slot;
    const uint32_t base = smb + OFF_SLOT0 + slot * SLOT_BYTES;
    if (lane == 0) MBAR_EXPECT_TX(mbar, 448u * 128u);
    __syncwarp();
    const float* W = (kc < 8) ? W_ih : W_hh;
    const size_t stride = (kc < 8) ? 256 : 128;
    const int col0 = ((kc < 8) ? kc : kc - 8) * 32;
#pragma unroll
    for (int i = 0; i < 14; ++i) {
        int r = i * 32 + lane;
        if (r < 384) {
            bulk_cp128(base + r * 144, W + (size_t)r * stride + col0, mbar);
        } else {
            int j = r - 384;
            const float* src;
            if (kc < 8) {
                int gr = row0 + j; if (gr >= B) gr = B - 1;
                src = messages + (size_t)gr * 256 + col0;
            } else {
                src = memory + (size_t)ids_s[j] * 128 + col0;
            }
            bulk_cp128(base + SLOT_A_OFF + j * 144, src, mbar);
        }
    }
}

// ---------------------------------------------------------------------------
// per-chunk MMA body; G2 = accumulator slot for the third gate (2=i_n, 3=h_n)
// A tile: 64 rows x 32 (stride 36 floats), W tile: 384 x 32 (stride 36)
// ---------------------------------------------------------------------------
template<int G2>
__device__ __forceinline__ void mma_chunk(float (&acc)[2][4][2][4],
                                          const float* A, const float* Ws,
                                          int wm, int wq, int lane) {
    const float* arow = A + (wm * 32 + (lane >> 2)) * 36 + (lane & 3);
    const float* bbas = Ws + (wq * 16 + (lane >> 2)) * 36 + (lane & 3);
#pragma unroll
    for (int k8 = 0; k8 < 4; ++k8) {
        float a[2][4];
#pragma unroll
        for (int mt = 0; mt < 2; ++mt) {
            const float* ap = arow + mt * 16 * 36 + k8 * 8;
            a[mt][0] = ap[0];
            a[mt][1] = ap[8 * 36];
            a[mt][2] = ap[4];
            a[mt][3] = ap[8 * 36 + 4];
        }
#pragma unroll
        for (int gate = 0; gate < 3; ++gate) {
            const int gi = (gate == 2) ? G2 : gate;
#pragma unroll
            for (int sub = 0; sub < 2; ++sub) {
                const float* bp = bbas + (gate * 128 + sub * 8) * 36 + k8 * 8;
                float b0 = bp[0], b1 = bp[4];
                mma_tf32(acc[0][gi][sub], a[0], b0, b1);
                mma_tf32(acc[1][gi][sub], a[1], b0, b1);
            }
        }
    }
}

// ---------------------------------------------------------------------------
// GRU kernel
// ---------------------------------------------------------------------------
__global__ void __launch_bounds__(THREADS, 1)
gru_update_kernel(const float* __restrict__ memory,
                  const int*   __restrict__ ids,
                  const float* __restrict__ messages,
                  const float* __restrict__ ts,
                  const float* __restrict__ W_ih,
                  const float* __restrict__ W_hh,
                  const float* __restrict__ b_ih,
                  const float* __restrict__ b_hh,
                  float* __restrict__ out_mem,
                  float* __restrict__ out_lu,
                  int B) {
    extern __shared__ char sm[];
    const uint32_t smb = (uint32_t)__cvta_generic_to_shared(sm);
    float* smf = (float*)sm;
    const int tid  = threadIdx.x;
    const int lane = tid & 31;
    const int warp = tid >> 5;
    const int row0 = blockIdx.x * BLOCK_M;
    const int wm = warp & 1;       // 32-row half
    const int wq = warp >> 1;      // 16-h-col group

    int* ids_s  = (int*)(sm + OFF_IDS);
    float* bias = (float*)(sm + OFF_BIAS);

    // ---- phase 0: ids, fused biases, mbarriers ----
    if (tid < BLOCK_M) {
        int gr = row0 + tid;
        ids_s[tid] = (gr < B) ? ids[gr] : 0;
    }
    {
        float v;
        if (tid < 256)      v = b_ih[tid] + b_hh[tid];      // r,z
        else if (tid < 384) v = b_ih[tid];                  // i_n
        else                v = b_hh[tid - 128];            // h_n
        bias[tid] = v;
    }
    if (tid == 0) {
        MBAR_INIT(smb + OFF_MBAR + 0, 1);
        MBAR_INIT(smb + OFF_MBAR + 8, 1);
        MBAR_INIT(smb + OFF_MBAR + 16, 1);
    }
    FENCE_ASYNC();
    __syncthreads();

    // ---- prolog: warp 0 stages chunks 0,1,2 ----
    if (warp == 0) {
        stage_bulk(smb, 0, messages, memory, ids_s, W_ih, W_hh, row0, B, lane);
        stage_bulk(smb, 1, messages, memory, ids_s, W_ih, W_hh, row0, B, lane);
        stage_bulk(smb, 2, messages, memory, ids_s, W_ih, W_hh, row0, B, lane);
    }

    float acc[2][4][2][4];                 // [mt][gate r/z/in/hn][sub][c]
#pragma unroll
    for (int mt = 0; mt < 2; ++mt)
#pragma unroll
        for (int g = 0; g < 4; ++g)
#pragma unroll
            for (int s = 0; s < 2; ++s)
#pragma unroll
                for (int c = 0; c < 4; ++c) acc[mt][g][s][c] = 0.0f;

    // ---- main loop: 12 K-chunks (0..7 = x / i_n, 8..11 = h / h_n) ----
    for (int kc = 0; kc < 12; ++kc) {
        const int slot = kc % 3;
        mbar_wait(smb + OFF_MBAR + 8 * slot, (kc / 3) & 1);
        const float* W = smf + (OFF_SLOT0 + slot * SLOT_BYTES) / 4;
        const float* A = W + SLOT_A_OFF / 4;
        if (kc < 8) mma_chunk<2>(acc, A, W, wm, wq, lane);
        else        mma_chunk<3>(acc, A, W, wm, wq, lane);
        __syncthreads();                  // all reads of this slot done
        if (warp == 0 && kc + 3 < 12)
            stage_bulk(smb, kc + 3, messages, memory, ids_s, W_ih, W_hh,
                       row0, B, lane);
    }

    // ---- register-resident GRU epilogue + scatter (h re-read from gmem) ----
#pragma unroll
    for (int mt = 0; mt < 2; ++mt) {
#pragma unroll
        for (int half = 0; half < 2; ++half) {     // acc c{0,1} vs c{2,3}
            int row_l = wm * 32 + mt * 16 + (lane >> 2) + half * 8;
            int gr = row0 + row_l;
            int node = ids_s[row_l];
            const float* hrow = memory + (size_t)node * 128;
            float* orow = out_mem + (size_t)node * 128;
            const int c0 = half * 2;
#pragma unroll
            for (int sub = 0; sub < 2; ++sub) {
                int hc = wq * 16 + sub * 8 + (lane & 3) * 2;
                float2 ho = *(const float2*)(hrow + hc);
                float2 br = *(const float2*)(bias + hc);
                float2 bz = *(const float2*)(bias + 128 + hc);
                float2 bi = *(const float2*)(bias + 256 + hc);
                float2 bh = *(const float2*)(bias + 384 + hc);
                float2 res;
                res.x = gru_one(acc[mt][0][sub][c0]     + br.x,
                                acc[mt][1][sub][c0]     + bz.x,
                                acc[mt][2][sub][c0]     + bi.x,
                                acc[mt][3][sub][c0]     + bh.x, ho.x);
                res.y = gru_one(acc[mt][0][sub][c0 + 1] + br.y,
                                acc[mt][1][sub][c0 + 1] + bz.y,
                                acc[mt][2][sub][c0 + 1] + bi.y,
                                acc[mt][3][sub][c0 + 1] + bh.y, ho.y);
                if (gr < B) *(float2*)(orow + hc) = res;
            }
        }
    }
    if (tid < BLOCK_M) {
        int gr = row0 + tid;
        if (gr < B) out_lu[ids_s[tid]] = ts[gr];
    }
}

// ---------------------------------------------------------------------------
extern "C" void kernel_launch(void* const* d_in, const int* in_sizes, int n_in,
                              void* d_out, int out_size) {
    const float* memory      = (const float*)d_in[0];
    const float* last_update = (const float*)d_in[1];
    const int*   ids         = (const int*)d_in[2];
    const float* messages    = (const float*)d_in[3];
    const float* ts          = (const float*)d_in[4];
    const float* W_ih        = (const float*)d_in[5];
    const float* W_hh        = (const float*)d_in[6];
    const float* b_ih        = (const float*)d_in[7];
    const float* b_hh        = (const float*)d_in[8];

    const int n_nodes = in_sizes[1];
    const int B       = in_sizes[2];

    float* out_mem = (float*)d_out;
    float* out_lu  = out_mem + (size_t)n_nodes * 128;

    // one-time setup on the (uncaptured) correctness call
    static bool inited = false;
    static cudaStream_t s_side;
    static cudaEvent_t e_fork, e_join;
    if (!inited) {
        cudaStreamCreateWithFlags(&s_side, cudaStreamNonBlocking);
        cudaEventCreateWithFlags(&e_fork, cudaEventDisableTiming);
        cudaEventCreateWithFlags(&e_join, cudaEventDisableTiming);
        cudaFuncSetAttribute(gru_update_kernel,
                             cudaFuncAttributeMaxDynamicSharedMemorySize,
                             SMEM_BYTES);
        inited = true;
    }

    // main stream: mask build + lu copy
    zero_mask_kernel<<<(MASK_WORDS + 255) / 256, 256>>>(MASK_WORDS);
    set_mask_kernel<<<(B + 255) / 256, 256>>>(ids, B);
    lu_copy_kernel<<<(n_nodes / 4 + 255) / 256, 256>>>(
        (const float4*)last_update, (float4*)out_lu, n_nodes / 4);

    // fork: masked bulk copy of memory on side stream, GRU on main stream
    cudaEventRecord(e_fork, 0);
    cudaStreamWaitEvent(s_side, e_fork, 0);
    {
        long long n4 = (long long)n_nodes * 32;
        copy_mem_kernel<<<(unsigned)((n4 + 255) / 256), 256, 0, s_side>>>(
            (const float4*)memory, (float4*)out_mem, n_nodes);
    }
    cudaEventRecord(e_join, s_side);

    int tiles = (B + BLOCK_M - 1) / BLOCK_M;
    gru_update_kernel<<<tiles, THREADS, SMEM_BYTES>>>(
        memory, ids, messages, ts, W_ih, W_hh, b_ih, b_hh,
        out_mem, out_lu, B);

    // join
    cudaStreamWaitEvent(0, e_join, 0);
}

// round 8
// speedup vs baseline: 5.6381x; 5.6381x over previous
#include <cuda_runtime.h>
#include <cstdint>

// ============================================================================
// SequenceMemoryUpdater v6.1 — v6 with alignment fixes:
//   * g_wpack alignas(128)  (cp.async.bulk needs 16B-aligned gmem src)
//   * HOLD row stride 132 floats (528B, 16B-divisible for cp.async.cg dst)
//
//   main stream: pack_w -> zero_mask -> set_mask -> lu_copy -> [fork] -> gru
//   side stream:                                    [fork] -> masked copy_mem
//
// GRU kernel (per 64-row tile):
//   gates[b,0:512]: 0..127 r, 128..255 z, 256..383 i_n (x-K), 384..511 h_n (h-K)
//   12 K-chunks of 32:
//     W chunk  = ONE cp.async.bulk (55296B) from packed g_wpack, mbarrier tx.
//     A chunk  = 512 cp16 (x-chunks only); h-chunks read the persistent HOLD.
//   mma.sync tf32 raw-fp32 operands (HW truncation), register GRU epilogue.
// ============================================================================

#define BLOCK_M   64
#define THREADS   512

// smem byte offsets
#define OFF_MBAR   0                    // 3 mbarriers (8B each)
#define OFF_BIAS   64                   // 512 floats
#define OFF_IDS    2112                 // 64 ints
#define OFF_HOLD   2432                 // 64 x 132 floats = 33792B
#define OFF_A      36224                // 2 slots x 64x36x4 = 9216B each
#define OFF_W      54656                // 3 slots x 384x36x4 = 55296B each
#define SMEM_BYTES 220544

#define W_SLOT_B   55296
#define A_SLOT_B   9216

#define MASK_WORDS 32768                // 1M nodes / 32
__device__ uint32_t g_mask[MASK_WORDS];
__device__ alignas(128) float g_wpack[12 * 384 * 36];  // packed W chunks

// ---- PTX helpers ----
#define MBAR_INIT(addr, cnt) \
    asm volatile("mbarrier.init.shared.b64 [%0], %1;" :: "r"(addr), "r"(cnt) : "memory")
#define MBAR_EXPECT_TX(addr, bytes) \
    asm volatile("mbarrier.arrive.expect_tx.shared.b64 _, [%0], %1;" \
                 :: "r"(addr), "r"(bytes) : "memory")
#define FENCE_ASYNC() asm volatile("fence.proxy.async.shared::cta;" ::: "memory")

__device__ __forceinline__ void mbar_wait(uint32_t addr, uint32_t parity) {
    asm volatile(
        "{\n\t.reg .pred P;\n"
        "W_%=:\n\t"
        "mbarrier.try_wait.parity.acquire.cta.shared::cta.b64 P, [%0], %1, 0x989680;\n\t"
        "@P bra.uni D_%=;\n\t"
        "bra.uni W_%=;\n"
        "D_%=:\n\t}"
        :: "r"(addr), "r"(parity) : "memory");
}

__device__ __forceinline__ void cp16(void* dst_smem, const void* src) {
    uint32_t d = (uint32_t)__cvta_generic_to_shared(dst_smem);
    asm volatile("cp.async.cg.shared.global [%0], [%1], 16;" :: "r"(d), "l"(src));
}
#define CP_COMMIT() asm volatile("cp.async.commit_group;" ::: "memory")
#define CP_WAIT(N)  asm volatile("cp.async.wait_group %0;" :: "n"(N) : "memory")

__device__ __forceinline__ void bulk_cp(uint32_t dst_smem, const void* src,
                                        uint32_t bytes, uint32_t mbar) {
    asm volatile(
        "cp.async.bulk.shared::cluster.global.mbarrier::complete_tx::bytes "
        "[%0], [%1], %2, [%3];"
        :: "r"(dst_smem), "l"(src), "r"(bytes), "r"(mbar) : "memory");
}

// raw fp32 bits fed as tf32 (HW truncates low 13 mantissa bits)
__device__ __forceinline__ void mma_tf32(float* d, const float* a,
                                         float b0, float b1) {
    asm volatile(
        "mma.sync.aligned.m16n8k8.row.col.f32.tf32.tf32.f32 "
        "{%0,%1,%2,%3}, {%4,%5,%6,%7}, {%8,%9}, {%0,%1,%2,%3};"
        : "+f"(d[0]), "+f"(d[1]), "+f"(d[2]), "+f"(d[3])
        : "r"(__float_as_uint(a[0])), "r"(__float_as_uint(a[1])),
          "r"(__float_as_uint(a[2])), "r"(__float_as_uint(a[3])),
          "r"(__float_as_uint(b0)),  "r"(__float_as_uint(b1)));
}

__device__ __forceinline__ float gru_one(float pr, float pz, float pin,
                                         float phn, float h) {
    float r = 1.0f / (1.0f + __expf(-pr));
    float z = 1.0f / (1.0f + __expf(-pz));
    float n = tanhf(fmaf(r, phn, pin));
    return fmaf(z, h - n, n);   // (1-z)*n + z*h
}

// ---------------------------------------------------------------------------
// W repack: g_wpack[kc][r][36]  (cols kc*32.. of W_ih / W_hh, pad = 0)
// ---------------------------------------------------------------------------
__global__ void pack_w_kernel(const float* __restrict__ W_ih,
                              const float* __restrict__ W_hh) {
    int idx = blockIdx.x * blockDim.x + threadIdx.x;   // one float4
    if (idx >= 12 * 384 * 9) return;
    int kc  = idx / (384 * 9);
    int rem = idx % (384 * 9);
    int r = rem / 9, c4 = rem % 9;
    float4 v = make_float4(0.f, 0.f, 0.f, 0.f);
    if (c4 < 8) {
        const float* W = (kc < 8) ? W_ih : W_hh;
        const size_t stride = (kc < 8) ? 256 : 128;
        const int col0 = ((kc < 8) ? kc : kc - 8) * 32;
        v = *(const float4*)(W + (size_t)r * stride + col0 + c4 * 4);
    }
    *(float4*)(g_wpack + ((size_t)(kc * 384 + r) * 36 + c4 * 4)) = v;
}

// ---------------------------------------------------------------------------
// mask + copies
// ---------------------------------------------------------------------------
__global__ void zero_mask_kernel(int n_words) {
    int i = blockIdx.x * blockDim.x + threadIdx.x;
    if (i < n_words) g_mask[i] = 0u;
}
__global__ void set_mask_kernel(const int* __restrict__ ids, int B) {
    int i = blockIdx.x * blockDim.x + threadIdx.x;
    if (i < B) {
        int node = ids[i];
        atomicOr(&g_mask[node >> 5], 1u << (node & 31));
    }
}
__global__ void lu_copy_kernel(const float4* __restrict__ lu,
                               float4* __restrict__ out, int n4) {
    int i = blockIdx.x * blockDim.x + threadIdx.x;
    if (i < n4) out[i] = lu[i];
}
__global__ void copy_mem_kernel(const float4* __restrict__ mem,
                                float4* __restrict__ out, int n_rows) {
    int idx = blockIdx.x * blockDim.x + threadIdx.x;   // float4 index
    int row = idx >> 5;
    if (row >= n_rows) return;
    if ((g_mask[row >> 5] >> (row & 31)) & 1u) return;
    out[idx] = mem[idx];
}

// ---------------------------------------------------------------------------
// per-chunk MMA body; G2 = accumulator slot of the third gate (2=i_n, 3=h_n),
// AS = A-tile row stride in floats
// ---------------------------------------------------------------------------
template<int G2, int AS>
__device__ __forceinline__ void mma_chunk(float (&acc)[2][4][2][4],
                                          const float* A, int Ac,
                                          const float* Ws,
                                          int wm, int wq, int lane) {
    const float* arow = A + (wm * 32 + (lane >> 2)) * AS + Ac + (lane & 3);
    const float* bbas = Ws + (wq * 16 + (lane >> 2)) * 36 + (lane & 3);
#pragma unroll
    for (int k8 = 0; k8 < 4; ++k8) {
        float a[2][4];
#pragma unroll
        for (int mt = 0; mt < 2; ++mt) {
            const float* ap = arow + mt * 16 * AS + k8 * 8;
            a[mt][0] = ap[0];
            a[mt][1] = ap[8 * AS];
            a[mt][2] = ap[4];
            a[mt][3] = ap[8 * AS + 4];
        }
#pragma unroll
        for (int gate = 0; gate < 3; ++gate) {
            const int gi = (gate == 2) ? G2 : gate;
#pragma unroll
            for (int sub = 0; sub < 2; ++sub) {
                const float* bp = bbas + (gate * 128 + sub * 8) * 36 + k8 * 8;
                float b0 = bp[0], b1 = bp[4];
                mma_tf32(acc[0][gi][sub], a[0], b0, b1);
                mma_tf32(acc[1][gi][sub], a[1], b0, b1);
            }
        }
    }
}

// ---------------------------------------------------------------------------
// GRU kernel
// ---------------------------------------------------------------------------
__global__ void __launch_bounds__(THREADS, 1)
gru_update_kernel(const float* __restrict__ memory,
                  const int*   __restrict__ ids,
                  const float* __restrict__ messages,
                  const float* __restrict__ ts,
                  const float* __restrict__ b_ih,
                  const float* __restrict__ b_hh,
                  float* __restrict__ out_mem,
                  float* __restrict__ out_lu,
                  int B) {
    extern __shared__ char sm[];
    const uint32_t smb = (uint32_t)__cvta_generic_to_shared(sm);
    float* smf = (float*)sm;
    const int tid  = threadIdx.x;
    const int lane = tid & 31;
    const int warp = tid >> 5;
    const int row0 = blockIdx.x * BLOCK_M;
    const int wm = warp & 1;       // 32-row half
    const int wq = warp >> 1;      // 16-h-col group

    int* ids_s  = (int*)(sm + OFF_IDS);
    float* bias = (float*)(sm + OFF_BIAS);
    float* hold = smf + OFF_HOLD / 4;

    // ---- phase 0: ids, fused biases, mbarriers ----
    if (tid < BLOCK_M) {
        int gr = row0 + tid;
        ids_s[tid] = (gr < B) ? ids[gr] : 0;
    }
    {
        float v;
        if (tid < 256)      v = b_ih[tid] + b_hh[tid];      // r,z
        else if (tid < 384) v = b_ih[tid];                  // i_n
        else                v = b_hh[tid - 128];            // h_n
        bias[tid] = v;
    }
    if (tid == 0) {
        MBAR_INIT(smb + OFF_MBAR + 0, 1);
        MBAR_INIT(smb + OFF_MBAR + 8, 1);
        MBAR_INIT(smb + OFF_MBAR + 16, 1);
    }
    FENCE_ASYNC();
    __syncthreads();

    // ---- prolog ----
    // group 0: HOLD gather (2048 cp16) + A chunk 0
#pragma unroll
    for (int i = 0; i < 4; ++i) {
        int idx = tid + i * THREADS;
        int m = idx >> 5, c = idx & 31;
        cp16(hold + m * 132 + c * 4, memory + (size_t)ids_s[m] * 128 + c * 4);
    }
    {
        int m = tid >> 3, c = tid & 7;
        int gr = row0 + m; if (gr >= B) gr = B - 1;
        cp16(smf + OFF_A / 4 + m * 36 + c * 4,
             messages + (size_t)gr * 256 + 0 * 32 + c * 4);
    }
    CP_COMMIT();
    // group 1: A chunk 1
    {
        int m = tid >> 3, c = tid & 7;
        int gr = row0 + m; if (gr >= B) gr = B - 1;
        cp16(smf + (OFF_A + A_SLOT_B) / 4 + m * 36 + c * 4,
             messages + (size_t)gr * 256 + 1 * 32 + c * 4);
    }
    CP_COMMIT();
    // W bulks: chunks 0,1,2 (thread 0)
    if (tid == 0) {
#pragma unroll
        for (int kc = 0; kc < 3; ++kc) {
            uint32_t mbar = smb + OFF_MBAR + 8 * kc;
            MBAR_EXPECT_TX(mbar, W_SLOT_B);
            bulk_cp(smb + OFF_W + kc * W_SLOT_B,
                    g_wpack + (size_t)kc * 384 * 36, W_SLOT_B, mbar);
        }
    }

    float acc[2][4][2][4];                 // [mt][gate r/z/in/hn][sub][c]
#pragma unroll
    for (int mt = 0; mt < 2; ++mt)
#pragma unroll
        for (int g = 0; g < 4; ++g)
#pragma unroll
            for (int s = 0; s < 2; ++s)
#pragma unroll
                for (int c = 0; c < 4; ++c) acc[mt][g][s][c] = 0.0f;

    // ---- main loop: 12 K-chunks (0..7 x / i_n, 8..11 h / h_n) ----
    for (int kc = 0; kc < 12; ++kc) {
        const int slot = kc % 3;
        if (kc < 7)       { CP_WAIT(1); }
        else if (kc == 7) { CP_WAIT(0); }
        mbar_wait(smb + OFF_MBAR + 8 * slot, (kc / 3) & 1);
        __syncthreads();                  // cross-thread A/W visibility

        const float* W = smf + (OFF_W + slot * W_SLOT_B) / 4;
        if (kc < 8)
            mma_chunk<2, 36>(acc, smf + (OFF_A + (kc & 1) * A_SLOT_B) / 4, 0,
                             W, wm, wq, lane);
        else
            mma_chunk<3, 132>(acc, hold, (kc - 8) * 32, W, wm, wq, lane);
        __syncthreads();                  // slot reads done

        // refill
        if (tid == 0 && kc + 3 < 12) {
            uint32_t mbar = smb + OFF_MBAR + 8 * slot;
            MBAR_EXPECT_TX(mbar, W_SLOT_B);
            bulk_cp(smb + OFF_W + slot * W_SLOT_B,
                    g_wpack + (size_t)(kc + 3) * 384 * 36, W_SLOT_B, mbar);
        }
        if (kc + 2 < 8) {
            int m = tid >> 3, c = tid & 7;
            int gr = row0 + m; if (gr >= B) gr = B - 1;
            cp16(smf + (OFF_A + ((kc + 2) & 1) * A_SLOT_B) / 4 + m * 36 + c * 4,
                 messages + (size_t)gr * 256 + (kc + 2) * 32 + c * 4);
            CP_COMMIT();
        }
    }

    // ---- register-resident GRU epilogue + scatter (h from HOLD) ----
#pragma unroll
    for (int mt = 0; mt < 2; ++mt) {
#pragma unroll
        for (int half = 0; half < 2; ++half) {     // acc c{0,1} vs c{2,3}
            int row_l = wm * 32 + mt * 16 + (lane >> 2) + half * 8;
            int gr = row0 + row_l;
            int node = ids_s[row_l];
            const float* hrow = hold + row_l * 132;
            float* orow = out_mem + (size_t)node * 128;
            const int c0 = half * 2;
#pragma unroll
            for (int sub = 0; sub < 2; ++sub) {
                int hc = wq * 16 + sub * 8 + (lane & 3) * 2;
                float2 ho = *(const float2*)(hrow + hc);
                float2 br = *(const float2*)(bias + hc);
                float2 bz = *(const float2*)(bias + 128 + hc);
                float2 bi = *(const float2*)(bias + 256 + hc);
                float2 bh = *(const float2*)(bias + 384 + hc);
                float2 res;
                res.x = gru_one(acc[mt][0][sub][c0]     + br.x,
                                acc[mt][1][sub][c0]     + bz.x,
                                acc[mt][2][sub][c0]     + bi.x,
                                acc[mt][3][sub][c0]     + bh.x, ho.x);
                res.y = gru_one(acc[mt][0][sub][c0 + 1] + br.y,
                                acc[mt][1][sub][c0 + 1] + bz.y,
                                acc[mt][2][sub][c0 + 1] + bi.y,
                                acc[mt][3][sub][c0 + 1] + bh.y, ho.y);
                if (gr < B) *(float2*)(orow + hc) = res;
            }
        }
    }
    if (tid < BLOCK_M) {
        int gr = row0 + tid;
        if (gr < B) out_lu[ids_s[tid]] = ts[gr];
    }
}

// ---------------------------------------------------------------------------
extern "C" void kernel_launch(void* const* d_in, const int* in_sizes, int n_in,
                              void* d_out, int out_size) {
    const float* memory      = (const float*)d_in[0];
    const float* last_update = (const float*)d_in[1];
    const int*   ids         = (const int*)d_in[2];
    const float* messages    = (const float*)d_in[3];
    const float* ts          = (const float*)d_in[4];
    const float* W_ih        = (const float*)d_in[5];
    const float* W_hh        = (const float*)d_in[6];
    const float* b_ih        = (const float*)d_in[7];
    const float* b_hh        = (const float*)d_in[8];

    const int n_nodes = in_sizes[1];
    const int B       = in_sizes[2];

    float* out_mem = (float*)d_out;
    float* out_lu  = out_mem + (size_t)n_nodes * 128;

    static bool inited = false;
    static cudaStream_t s_side;
    static cudaEvent_t e_fork, e_join;
    if (!inited) {
        cudaStreamCreateWithFlags(&s_side, cudaStreamNonBlocking);
        cudaEventCreateWithFlags(&e_fork, cudaEventDisableTiming);
        cudaEventCreateWithFlags(&e_join, cudaEventDisableTiming);
        cudaFuncSetAttribute(gru_update_kernel,
                             cudaFuncAttributeMaxDynamicSharedMemorySize,
                             SMEM_BYTES);
        inited = true;
    }

    // main stream: W pack, mask build, lu copy
    pack_w_kernel<<<(12 * 384 * 9 + 255) / 256, 256>>>(W_ih, W_hh);
    zero_mask_kernel<<<(MASK_WORDS + 255) / 256, 256>>>(MASK_WORDS);
    set_mask_kernel<<<(B + 255) / 256, 256>>>(ids, B);
    lu_copy_kernel<<<(n_nodes / 4 + 255) / 256, 256>>>(
        (const float4*)last_update, (float4*)out_lu, n_nodes / 4);

    // fork: masked bulk copy of memory on side stream
    cudaEventRecord(e_fork, 0);
    cudaStreamWaitEvent(s_side, e_fork, 0);
    {
        long long n4 = (long long)n_nodes * 32;
        copy_mem_kernel<<<(unsigned)((n4 + 255) / 256), 256, 0, s_side>>>(
            (const float4*)memory, (float4*)out_mem, n_nodes);
    }
    cudaEventRecord(e_join, s_side);

    // main stream: GRU
    int tiles = (B + BLOCK_M - 1) / BLOCK_M;
    gru_update_kernel<<<tiles, THREADS, SMEM_BYTES>>>(
        memory, ids, messages, ts, b_ih, b_hh, out_mem, out_lu, B);

    // join
    cudaStreamWaitEvent(0, e_join, 0);
}

// round 9
// speedup vs baseline: 6.0630x; 1.0754x over previous
#include <cuda_runtime.h>
#include <cstdint>

// ============================================================================
// SequenceMemoryUpdater v7 — fragment-packed W via direct LDG (no W smem)
//
//   main stream: pack_w -> zero_mask -> set_mask -> lu_copy -> [fork] -> gru
//   side stream:                                    [fork] -> masked copy_mem
//
// GRU kernel (per 64-row tile), 512 threads = 16 warps:
//   warp wq owns ALL 64 rows x cols [wq*8, wq*8+8) of EACH gate (r,z,in,hn)
//   -> W fragments warp-private & disjoint; loaded straight from g_wfrag
//      (fragment-ordered, L2-resident) as 6 x LDG.128 per chunk per thread.
//   A (messages) staged via cp.async 3-slot ring; h rows in persistent HOLD.
//   One __syncthreads per x-chunk; h-chunks (8..11) sync-free.
//   mma.sync tf32 raw-fp32 operands (HW truncation), register GRU epilogue.
// ============================================================================

#define BLOCK_M   64
#define THREADS   512

// smem byte offsets
#define OFF_BIAS   0                    // 512 floats = 2048B
#define OFF_IDS    2048                 // 64 ints = 256B
#define OFF_HOLD   2304                 // 64 x 132 floats = 33792B
#define OFF_A      36096                // 3 slots x 64x36x4 = 9216B each
#define SMEM_BYTES 63744

#define A_SLOT_B   9216

#define MASK_WORDS 32768                // 1M nodes / 32
__device__ uint32_t g_mask[MASK_WORDS];
// fragment-packed W: [kc][wq][j(0..5)][lane] float4
// float4 (kc,wq,j,lane) holds floats f=4j..4j+3: k8g=f>>1, b=f&1,
//   k8=k8g/3, gate=k8g%3, value = W[gate*128 + wq*8 + (lane>>2)]
//                                  [kc_col0 + k8*8 + (lane&3) + b*4]
__device__ alignas(128) float4 g_wfrag[12 * 16 * 6 * 32];

// ---- PTX helpers ----
__device__ __forceinline__ void cp16(void* dst_smem, const void* src) {
    uint32_t d = (uint32_t)__cvta_generic_to_shared(dst_smem);
    asm volatile("cp.async.cg.shared.global [%0], [%1], 16;" :: "r"(d), "l"(src));
}
#define CP_COMMIT() asm volatile("cp.async.commit_group;" ::: "memory")
#define CP_WAIT(N)  asm volatile("cp.async.wait_group %0;" :: "n"(N) : "memory")

// raw fp32 bits fed as tf32 (HW truncates low 13 mantissa bits)
__device__ __forceinline__ void mma_tf32(float* d, const float* a,
                                         float b0, float b1) {
    asm volatile(
        "mma.sync.aligned.m16n8k8.row.col.f32.tf32.tf32.f32 "
        "{%0,%1,%2,%3}, {%4,%5,%6,%7}, {%8,%9}, {%0,%1,%2,%3};"
        : "+f"(d[0]), "+f"(d[1]), "+f"(d[2]), "+f"(d[3])
        : "r"(__float_as_uint(a[0])), "r"(__float_as_uint(a[1])),
          "r"(__float_as_uint(a[2])), "r"(__float_as_uint(a[3])),
          "r"(__float_as_uint(b0)),  "r"(__float_as_uint(b1)));
}

__device__ __forceinline__ float gru_one(float pr, float pz, float pin,
                                         float phn, float h) {
    float r = 1.0f / (1.0f + __expf(-pr));
    float z = 1.0f / (1.0f + __expf(-pz));
    float n = tanhf(fmaf(r, phn, pin));
    return fmaf(z, h - n, n);   // (1-z)*n + z*h
}

// ---------------------------------------------------------------------------
// W fragment repack: one thread per float4 of g_wfrag
// ---------------------------------------------------------------------------
__global__ void pack_w_kernel(const float* __restrict__ W_ih,
                              const float* __restrict__ W_hh) {
    int idx = blockIdx.x * blockDim.x + threadIdx.x;
    if (idx >= 12 * 16 * 6 * 32) return;
    int lane = idx & 31;
    int j    = (idx >> 5) % 6;
    int wq   = (idx >> 5) / 6 % 16;
    int kc   = idx / (6 * 32 * 16);
    const float* W = (kc < 8) ? W_ih : W_hh;
    const int stride = (kc < 8) ? 256 : 128;
    const int col0   = ((kc < 8) ? kc : kc - 8) * 32;
    float v[4];
#pragma unroll
    for (int c = 0; c < 4; ++c) {
        int f = j * 4 + c;
        int k8g = f >> 1, b = f & 1;
        int k8 = k8g / 3, gate = k8g % 3;
        int nrow = gate * 128 + wq * 8 + (lane >> 2);
        int k = col0 + k8 * 8 + (lane & 3) + b * 4;
        v[c] = W[(size_t)nrow * stride + k];
    }
    g_wfrag[idx] = make_float4(v[0], v[1], v[2], v[3]);
}

// ---------------------------------------------------------------------------
// mask + copies
// ---------------------------------------------------------------------------
__global__ void zero_mask_kernel(int n_words) {
    int i = blockIdx.x * blockDim.x + threadIdx.x;
    if (i < n_words) g_mask[i] = 0u;
}
__global__ void set_mask_kernel(const int* __restrict__ ids, int B) {
    int i = blockIdx.x * blockDim.x + threadIdx.x;
    if (i < B) {
        int node = ids[i];
        atomicOr(&g_mask[node >> 5], 1u << (node & 31));
    }
}
__global__ void lu_copy_kernel(const float4* __restrict__ lu,
                               float4* __restrict__ out, int n4) {
    int i = blockIdx.x * blockDim.x + threadIdx.x;
    if (i < n4) out[i] = lu[i];
}
__global__ void copy_mem_kernel(const float4* __restrict__ mem,
                                float4* __restrict__ out, int n_rows) {
    int idx = blockIdx.x * blockDim.x + threadIdx.x;   // float4 index
    int row = idx >> 5;
    if (row >= n_rows) return;
    if ((g_mask[row >> 5] >> (row & 31)) & 1u) return;
    out[idx] = mem[idx];
}

// ---------------------------------------------------------------------------
// per-chunk MMA: wv = 6 preloaded W float4s; G2 = third-gate acc slot,
// AS = A row stride (floats)
// ---------------------------------------------------------------------------
template<int G2, int AS>
__device__ __forceinline__ void mma_chunk(float (&acc)[4][4][4],
                                          const float* A, int Ac,
                                          const float4 (&wv)[6], int lane) {
    const float* arow = A + (lane >> 2) * AS + Ac + (lane & 3);
#pragma unroll
    for (int k8 = 0; k8 < 4; ++k8) {
        float a[4][4];
#pragma unroll
        for (int mt = 0; mt < 4; ++mt) {
            const float* ap = arow + mt * 16 * AS + k8 * 8;
            a[mt][0] = ap[0];
            a[mt][1] = ap[8 * AS];
            a[mt][2] = ap[4];
            a[mt][3] = ap[8 * AS + 4];
        }
#pragma unroll
        for (int gate = 0; gate < 3; ++gate) {
            const int gi = (gate == 2) ? G2 : gate;
            const int k8g = k8 * 3 + gate;
            float b0, b1;
            if (k8g & 1) { b0 = wv[k8g >> 1].z; b1 = wv[k8g >> 1].w; }
            else         { b0 = wv[k8g >> 1].x; b1 = wv[k8g >> 1].y; }
#pragma unroll
            for (int mt = 0; mt < 4; ++mt)
                mma_tf32(acc[mt][gi], a[mt], b0, b1);
        }
    }
}

// ---------------------------------------------------------------------------
// GRU kernel
// ---------------------------------------------------------------------------
__global__ void __launch_bounds__(THREADS, 1)
gru_update_kernel(const float* __restrict__ memory,
                  const int*   __restrict__ ids,
                  const float* __restrict__ messages,
                  const float* __restrict__ ts,
                  const float* __restrict__ b_ih,
                  const float* __restrict__ b_hh,
                  float* __restrict__ out_mem,
                  float* __restrict__ out_lu,
                  int B) {
    extern __shared__ char sm[];
    float* smf = (float*)sm;
    const int tid  = threadIdx.x;
    const int lane = tid & 31;
    const int wq   = tid >> 5;              // warp = col group
    const int row0 = blockIdx.x * BLOCK_M;

    int* ids_s  = (int*)(sm + OFF_IDS);
    float* bias = (float*)(sm + OFF_BIAS);
    float* hold = smf + OFF_HOLD / 4;

    // ---- phase 0: ids + fused biases ----
    if (tid < BLOCK_M) {
        int gr = row0 + tid;
        ids_s[tid] = (gr < B) ? ids[gr] : 0;
    }
    {
        float v;
        if (tid < 256)      v = b_ih[tid] + b_hh[tid];      // r,z
        else if (tid < 384) v = b_ih[tid];                  // i_n
        else                v = b_hh[tid - 128];            // h_n
        bias[tid] = v;
    }
    __syncthreads();

    // ---- prolog: HOLD gather + A chunks 0,1 (slots 0,1) ----
#pragma unroll
    for (int i = 0; i < 4; ++i) {            // 2048 cp16 for HOLD
        int idx = tid + i * THREADS;
        int m = idx >> 5, c = idx & 31;
        cp16(hold + m * 132 + c * 4, memory + (size_t)ids_s[m] * 128 + c * 4);
    }
    {
        int m = tid >> 3, c = tid & 7;
        int gr = row0 + m; if (gr >= B) gr = B - 1;
        cp16(smf + OFF_A / 4 + m * 36 + c * 4,
             messages + (size_t)gr * 256 + c * 4);
    }
    CP_COMMIT();
    {
        int m = tid >> 3, c = tid & 7;
        int gr = row0 + m; if (gr >= B) gr = B - 1;
        cp16(smf + (OFF_A + A_SLOT_B) / 4 + m * 36 + c * 4,
             messages + (size_t)gr * 256 + 32 + c * 4);
    }
    CP_COMMIT();

    float acc[4][4][4];                      // [mt][gate r/z/in/hn][c]
#pragma unroll
    for (int mt = 0; mt < 4; ++mt)
#pragma unroll
        for (int g = 0; g < 4; ++g)
#pragma unroll
            for (int c = 0; c < 4; ++c) acc[mt][g][c] = 0.0f;

    const float4* wbase = g_wfrag + (size_t)wq * 6 * 32 + lane;

    // ---- main loop: 12 K-chunks (0..7 x / i_n, 8..11 h / h_n) ----
#pragma unroll 1
    for (int kc = 0; kc < 12; ++kc) {
        // W fragments: 6 LDG.128, hoisted above the sync to hide L2 latency
        float4 wv[6];
        const float4* wf = wbase + (size_t)kc * 16 * 6 * 32;
#pragma unroll
        for (int j = 0; j < 6; ++j) wv[j] = wf[j * 32];

        if (kc < 8) {
            if (kc < 7) { CP_WAIT(1); } else { CP_WAIT(0); }
            __syncthreads();                 // A(kc) visible CTA-wide
        }

        if (kc < 8)
            mma_chunk<2, 36>(acc, smf + (OFF_A + (kc % 3) * A_SLOT_B) / 4, 0,
                             wv, lane);
        else
            mma_chunk<3, 132>(acc, hold, (kc - 8) * 32, wv, lane);

        // stage A(kc+2) into slot (kc+2)%3 — that slot was read at chunk
        // kc-1, which every thread finished before this chunk's sync
        if (kc + 2 < 8) {
            int m = tid >> 3, c = tid & 7;
            int gr = row0 + m; if (gr >= B) gr = B - 1;
            cp16(smf + (OFF_A + ((kc + 2) % 3) * A_SLOT_B) / 4 + m * 36 + c * 4,
                 messages + (size_t)gr * 256 + (kc + 2) * 32 + c * 4);
            CP_COMMIT();
        }
    }

    // ---- register-resident GRU epilogue + scatter (h from HOLD) ----
#pragma unroll
    for (int mt = 0; mt < 4; ++mt) {
#pragma unroll
        for (int half = 0; half < 2; ++half) {     // acc c{0,1} vs c{2,3}
            int row_l = mt * 16 + (lane >> 2) + half * 8;
            int gr = row0 + row_l;
            int node = ids_s[row_l];
            const float* hrow = hold + row_l * 132;
            float* orow = out_mem + (size_t)node * 128;
            const int c0 = half * 2;
            int hc = wq * 8 + (lane & 3) * 2;
            float2 ho = *(const float2*)(hrow + hc);
            float2 br = *(const float2*)(bias + hc);
            float2 bz = *(const float2*)(bias + 128 + hc);
            float2 bi = *(const float2*)(bias + 256 + hc);
            float2 bh = *(const float2*)(bias + 384 + hc);
            float2 res;
            res.x = gru_one(acc[mt][0][c0]     + br.x,
                            acc[mt][1][c0]     + bz.x,
                            acc[mt][2][c0]     + bi.x,
                            acc[mt][3][c0]     + bh.x, ho.x);
            res.y = gru_one(acc[mt][0][c0 + 1] + br.y,
                            acc[mt][1][c0 + 1] + bz.y,
                            acc[mt][2][c0 + 1] + bi.y,
                            acc[mt][3][c0 + 1] + bh.y, ho.y);
            if (gr < B) *(float2*)(orow + hc) = res;
        }
    }
    if (tid < BLOCK_M) {
        int gr = row0 + tid;
        if (gr < B) out_lu[ids_s[tid]] = ts[gr];
    }
}

// ---------------------------------------------------------------------------
extern "C" void kernel_launch(void* const* d_in, const int* in_sizes, int n_in,
                              void* d_out, int out_size) {
    const float* memory      = (const float*)d_in[0];
    const float* last_update = (const float*)d_in[1];
    const int*   ids         = (const int*)d_in[2];
    const float* messages    = (const float*)d_in[3];
    const float* ts          = (const float*)d_in[4];
    const float* W_ih        = (const float*)d_in[5];
    const float* W_hh        = (const float*)d_in[6];
    const float* b_ih        = (const float*)d_in[7];
    const float* b_hh        = (const float*)d_in[8];

    const int n_nodes = in_sizes[1];
    const int B       = in_sizes[2];

    float* out_mem = (float*)d_out;
    float* out_lu  = out_mem + (size_t)n_nodes * 128;

    static bool inited = false;
    static cudaStream_t s_side;
    static cudaEvent_t e_fork, e_join;
    if (!inited) {
        cudaStreamCreateWithFlags(&s_side, cudaStreamNonBlocking);
        cudaEventCreateWithFlags(&e_fork, cudaEventDisableTiming);
        cudaEventCreateWithFlags(&e_join, cudaEventDisableTiming);
        cudaFuncSetAttribute(gru_update_kernel,
                             cudaFuncAttributeMaxDynamicSharedMemorySize,
                             SMEM_BYTES);
        inited = true;
    }

    // main stream: W fragment pack, mask build, lu copy
    pack_w_kernel<<<(12 * 16 * 6 * 32 + 255) / 256, 256>>>(W_ih, W_hh);
    zero_mask_kernel<<<(MASK_WORDS + 255) / 256, 256>>>(MASK_WORDS);
    set_mask_kernel<<<(B + 255) / 256, 256>>>(ids, B);
    lu_copy_kernel<<<(n_nodes / 4 + 255) / 256, 256>>>(
        (const float4*)last_update, (float4*)out_lu, n_nodes / 4);

    // fork: masked bulk copy of memory on side stream
    cudaEventRecord(e_fork, 0);
    cudaStreamWaitEvent(s_side, e_fork, 0);
    {
        long long n4 = (long long)n_nodes * 32;
        copy_mem_kernel<<<(unsigned)((n4 + 255) / 256), 256, 0, s_side>>>(
            (const float4*)memory, (float4*)out_mem, n_nodes);
    }
    cudaEventRecord(e_join, s_side);

    // main stream: GRU
    int tiles = (B + BLOCK_M - 1) / BLOCK_M;
    gru_update_kernel<<<tiles, THREADS, SMEM_BYTES>>>(
        memory, ids, messages, ts, b_ih, b_hh, out_mem, out_lu, B);

    // join
    cudaStreamWaitEvent(0, e_join, 0);
}

// round 10
// speedup vs baseline: 7.4608x; 1.2305x over previous
#include <cuda_runtime.h>
#include <cuda_fp16.h>
#include <cstdint>

// ============================================================================
// SequenceMemoryUpdater v8 — fp16 mma.sync (m16n8k16), ldmatrix A-frags,
//                            sync-free mainloop, overlapped masked copy
//
//   main stream: pack_w -> zero_mask -> set_mask -> lu_copy -> [fork] -> gru
//   side stream:                                    [fork] -> masked copy_mem
//
// GRU kernel (per 64-row tile), 512 threads = 16 warps:
//   prolog: gather h rows + messages, convert fp32 -> fp16 into smem. ONE sync.
//   mainloop (12 K-chunks of 32, fully unrolled, NO syncs):
//     W: fragment-packed fp16 in gmem (L2-resident), 3 x LDG.128 /thread/chunk
//     A: ldmatrix.x4 from fp16 smem (8 per warp per chunk)
//     24 x mma.sync.m16n8k16.f32.f16.f16.f32 per warp per chunk
//   epilogue: register-resident GRU (h_old re-read fp32 from gmem, L2-hot).
//   warp wq owns all 64 rows x cols [wq*8, wq*8+8) of each gate.
// ============================================================================

#define BLOCK_M   64
#define THREADS   512

// smem byte offsets
#define OFF_BIAS   0                    // 512 floats = 2048B
#define OFF_IDS    2048                 // 64 ints = 256B
#define OFF_MSG    2304                 // 64 rows x 264 halves = 33792B
#define OFF_HOLD   36096                // 64 rows x 136 halves = 17408B
#define SMEM_BYTES 53504

#define MSG_STRIDE  264                 // halves (528B row: 16B-mult, lm-conflict-free)
#define HOLD_STRIDE 136                 // halves (272B row)

#define MASK_WORDS 32768                // 1M nodes / 32
__device__ uint32_t g_mask[MASK_WORDS];
// fragment-packed fp16 W: [kc][wq][gate(3)][lane] uint4
//   uint4 = b-frag regs {g16=0:b0, g16=0:b1, g16=1:b0, g16=1:b1}
__device__ alignas(128) uint4 g_wfrag[12 * 16 * 3 * 32];

// ---- helpers ----
__device__ __forceinline__ uint32_t pack2(float x, float y) {
    __half2 h = __floats2half2_rn(x, y);
    return *(uint32_t*)&h;
}

__device__ __forceinline__ void ldmatrix_x4(uint32_t* a, uint32_t addr) {
    asm volatile(
        "ldmatrix.sync.aligned.m8n8.x4.shared.b16 {%0,%1,%2,%3}, [%4];"
        : "=r"(a[0]), "=r"(a[1]), "=r"(a[2]), "=r"(a[3]) : "r"(addr));
}

__device__ __forceinline__ void mma_f16(float* d, const uint32_t* a,
                                        uint32_t b0, uint32_t b1) {
    asm volatile(
        "mma.sync.aligned.m16n8k16.row.col.f32.f16.f16.f32 "
        "{%0,%1,%2,%3}, {%4,%5,%6,%7}, {%8,%9}, {%0,%1,%2,%3};"
        : "+f"(d[0]), "+f"(d[1]), "+f"(d[2]), "+f"(d[3])
        : "r"(a[0]), "r"(a[1]), "r"(a[2]), "r"(a[3]), "r"(b0), "r"(b1));
}

__device__ __forceinline__ float gru_one(float pr, float pz, float pin,
                                         float phn, float h) {
    float r = 1.0f / (1.0f + __expf(-pr));
    float z = 1.0f / (1.0f + __expf(-pz));
    float n = tanhf(fmaf(r, phn, pin));
    return fmaf(z, h - n, n);   // (1-z)*n + z*h
}

// ---------------------------------------------------------------------------
// W fragment repack (fp16): one thread per uint4 of g_wfrag
// b-frag for m16n8k16 col-major B (= W^T):
//   reg r (0/1), half i (0/1): k = g16*16 + r*8 + (lane%4)*2 + i, n = lane/4
// ---------------------------------------------------------------------------
__global__ void pack_w_kernel(const float* __restrict__ W_ih,
                              const float* __restrict__ W_hh) {
    int idx = blockIdx.x * blockDim.x + threadIdx.x;
    if (idx >= 12 * 16 * 3 * 32) return;
    int lane = idx & 31;
    int gate = (idx >> 5) % 3;
    int wq   = (idx >> 5) / 3 % 16;
    int kc   = idx / (32 * 3 * 16);
    const float* W = (kc < 8) ? W_ih : W_hh;
    const int stride = (kc < 8) ? 256 : 128;
    const int col0   = ((kc < 8) ? kc : kc - 8) * 32;
    const int nrow   = gate * 128 + wq * 8 + (lane >> 2);
    uint32_t q[4];
#pragma unroll
    for (int qi = 0; qi < 4; ++qi) {
        int g16 = qi >> 1, r = qi & 1;
        int k = col0 + g16 * 16 + r * 8 + (lane & 3) * 2;
        q[qi] = pack2(W[(size_t)nrow * stride + k],
                      W[(size_t)nrow * stride + k + 1]);
    }
    g_wfrag[idx] = make_uint4(q[0], q[1], q[2], q[3]);
}

// ---------------------------------------------------------------------------
// mask + copies
// ---------------------------------------------------------------------------
__global__ void zero_mask_kernel(int n_words) {
    int i = blockIdx.x * blockDim.x + threadIdx.x;
    if (i < n_words) g_mask[i] = 0u;
}
__global__ void set_mask_kernel(const int* __restrict__ ids, int B) {
    int i = blockIdx.x * blockDim.x + threadIdx.x;
    if (i < B) {
        int node = ids[i];
        atomicOr(&g_mask[node >> 5], 1u << (node & 31));
    }
}
__global__ void lu_copy_kernel(const float4* __restrict__ lu,
                               float4* __restrict__ out, int n4) {
    int i = blockIdx.x * blockDim.x + threadIdx.x;
    if (i < n4) out[i] = lu[i];
}
__global__ void copy_mem_kernel(const float4* __restrict__ mem,
                                float4* __restrict__ out, int n_rows) {
    int idx = blockIdx.x * blockDim.x + threadIdx.x;   // float4 index
    int row = idx >> 5;
    if (row >= n_rows) return;
    if ((g_mask[row >> 5] >> (row & 31)) & 1u) return;
    out[idx] = mem[idx];
}

// ---------------------------------------------------------------------------
// GRU kernel
// ---------------------------------------------------------------------------
__global__ void __launch_bounds__(THREADS, 1)
gru_update_kernel(const float* __restrict__ memory,
                  const int*   __restrict__ ids,
                  const float* __restrict__ messages,
                  const float* __restrict__ ts,
                  const float* __restrict__ b_ih,
                  const float* __restrict__ b_hh,
                  float* __restrict__ out_mem,
                  float* __restrict__ out_lu,
                  int B) {
    extern __shared__ char sm[];
    const uint32_t smb = (uint32_t)__cvta_generic_to_shared(sm);
    const int tid  = threadIdx.x;
    const int lane = tid & 31;
    const int wq   = tid >> 5;              // warp = col group
    const int row0 = blockIdx.x * BLOCK_M;

    int* ids_s  = (int*)(sm + OFF_IDS);
    float* bias = (float*)(sm + OFF_BIAS);

    // ---- phase 0: ids + fused biases ----
    if (tid < BLOCK_M) {
        int gr = row0 + tid;
        ids_s[tid] = (gr < B) ? ids[gr] : 0;
    }
    {
        float v;
        if (tid < 256)      v = b_ih[tid] + b_hh[tid];      // r,z
        else if (tid < 384) v = b_ih[tid];                  // i_n
        else                v = b_hh[tid - 128];            // h_n
        bias[tid] = v;
    }
    __syncthreads();

    // ---- prolog: load + convert messages and h rows to fp16 smem ----
    {
        // messages: thread -> row tid/8, 32 cols at (tid%8)*32
        int r = tid >> 3, c0 = (tid & 7) * 32;
        int gr = row0 + r; if (gr >= B) gr = B - 1;
        const float4* src = (const float4*)(messages + (size_t)gr * 256 + c0);
        float4 v[8];
#pragma unroll
        for (int j = 0; j < 8; ++j) v[j] = src[j];
        uint4* dst = (uint4*)(sm + OFF_MSG + (r * MSG_STRIDE + c0) * 2);
#pragma unroll
        for (int j = 0; j < 4; ++j)
            dst[j] = make_uint4(pack2(v[2*j].x,   v[2*j].y),
                                pack2(v[2*j].z,   v[2*j].w),
                                pack2(v[2*j+1].x, v[2*j+1].y),
                                pack2(v[2*j+1].z, v[2*j+1].w));
        // h rows: thread -> row tid/8, 16 cols at (tid%8)*16
        int hc0 = (tid & 7) * 16;
        const float4* hs = (const float4*)(memory +
                               (size_t)ids_s[r] * 128 + hc0);
        float4 hv[4];
#pragma unroll
        for (int j = 0; j < 4; ++j) hv[j] = hs[j];
        uint4* hd = (uint4*)(sm + OFF_HOLD + (r * HOLD_STRIDE + hc0) * 2);
#pragma unroll
        for (int j = 0; j < 2; ++j)
            hd[j] = make_uint4(pack2(hv[2*j].x,   hv[2*j].y),
                               pack2(hv[2*j].z,   hv[2*j].w),
                               pack2(hv[2*j+1].x, hv[2*j+1].y),
                               pack2(hv[2*j+1].z, hv[2*j+1].w));
    }
    __syncthreads();    // the ONLY mainloop-relevant barrier

    float acc[4][4][4];                      // [mt][gate r/z/in/hn][c]
#pragma unroll
    for (int mt = 0; mt < 4; ++mt)
#pragma unroll
        for (int g = 0; g < 4; ++g)
#pragma unroll
            for (int c = 0; c < 4; ++c) acc[mt][g][c] = 0.0f;

    const uint4* wbase = g_wfrag + (size_t)wq * 3 * 32 + lane;
    // ldmatrix per-thread row/segment offsets
    const int lm_row = lane & 15;
    const int lm_seg = (lane >> 4) * 8;      // halves

    // ---- mainloop: 12 chunks, no syncs ----
#pragma unroll
    for (int kc = 0; kc < 12; ++kc) {
        uint4 wv[3];
        const uint4* wf = wbase + (size_t)kc * 16 * 3 * 32;
        wv[0] = wf[0]; wv[1] = wf[32]; wv[2] = wf[64];

        uint32_t abase;
        if (kc < 8)
            abase = smb + OFF_MSG +
                    (lm_row * MSG_STRIDE + kc * 32 + lm_seg) * 2;
        else
            abase = smb + OFF_HOLD +
                    (lm_row * HOLD_STRIDE + (kc - 8) * 32 + lm_seg) * 2;
        const int astride = (kc < 8) ? MSG_STRIDE : HOLD_STRIDE;
        const int G2 = (kc < 8) ? 2 : 3;

#pragma unroll
        for (int g16 = 0; g16 < 2; ++g16) {
            uint32_t a[4][4];
#pragma unroll
            for (int mt = 0; mt < 4; ++mt)
                ldmatrix_x4(a[mt], abase + (mt * 16 * astride + g16 * 16) * 2);
#pragma unroll
            for (int gate = 0; gate < 3; ++gate) {
                const int gi = (gate == 2) ? G2 : gate;
                uint32_t b0 = g16 ? wv[gate].z : wv[gate].x;
                uint32_t b1 = g16 ? wv[gate].w : wv[gate].y;
#pragma unroll
                for (int mt = 0; mt < 4; ++mt)
                    mma_f16(acc[mt][gi], a[mt], b0, b1);
            }
        }
    }

    // ---- register-resident GRU epilogue + scatter (h_old fp32 from gmem) ----
#pragma unroll
    for (int mt = 0; mt < 4; ++mt) {
#pragma unroll
        for (int half = 0; half < 2; ++half) {     // acc c{0,1} vs c{2,3}
            int row_l = mt * 16 + (lane >> 2) + half * 8;
            int gr = row0 + row_l;
            int node = ids_s[row_l];
            float* orow = out_mem + (size_t)node * 128;
            const int c0 = half * 2;
            int hc = wq * 8 + (lane & 3) * 2;
            float2 ho = *(const float2*)(memory + (size_t)node * 128 + hc);
            float2 br = *(const float2*)(bias + hc);
            float2 bz = *(const float2*)(bias + 128 + hc);
            float2 bi = *(const float2*)(bias + 256 + hc);
            float2 bh = *(const float2*)(bias + 384 + hc);
            float2 res;
            res.x = gru_one(acc[mt][0][c0]     + br.x,
                            acc[mt][1][c0]     + bz.x,
                            acc[mt][2][c0]     + bi.x,
                            acc[mt][3][c0]     + bh.x, ho.x);
            res.y = gru_one(acc[mt][0][c0 + 1] + br.y,
                            acc[mt][1][c0 + 1] + bz.y,
                            acc[mt][2][c0 + 1] + bi.y,
                            acc[mt][3][c0 + 1] + bh.y, ho.y);
            if (gr < B) *(float2*)(orow + hc) = res;
        }
    }
    if (tid < BLOCK_M) {
        int gr = row0 + tid;
        if (gr < B) out_lu[ids_s[tid]] = ts[gr];
    }
}

// ---------------------------------------------------------------------------
extern "C" void kernel_launch(void* const* d_in, const int* in_sizes, int n_in,
                              void* d_out, int out_size) {
    const float* memory      = (const float*)d_in[0];
    const float* last_update = (const float*)d_in[1];
    const int*   ids         = (const int*)d_in[2];
    const float* messages    = (const float*)d_in[3];
    const float* ts          = (const float*)d_in[4];
    const float* W_ih        = (const float*)d_in[5];
    const float* W_hh        = (const float*)d_in[6];
    const float* b_ih        = (const float*)d_in[7];
    const float* b_hh        = (const float*)d_in[8];

    const int n_nodes = in_sizes[1];
    const int B       = in_sizes[2];

    float* out_mem = (float*)d_out;
    float* out_lu  = out_mem + (size_t)n_nodes * 128;

    static bool inited = false;
    static cudaStream_t s_side;
    static cudaEvent_t e_fork, e_join;
    if (!inited) {
        cudaStreamCreateWithFlags(&s_side, cudaStreamNonBlocking);
        cudaEventCreateWithFlags(&e_fork, cudaEventDisableTiming);
        cudaEventCreateWithFlags(&e_join, cudaEventDisableTiming);
        cudaFuncSetAttribute(gru_update_kernel,
                             cudaFuncAttributeMaxDynamicSharedMemorySize,
                             SMEM_BYTES);
        inited = true;
    }

    // main stream: W fragment pack, mask build, lu copy
    pack_w_kernel<<<(12 * 16 * 3 * 32 + 255) / 256, 256>>>(W_ih, W_hh);
    zero_mask_kernel<<<(MASK_WORDS + 255) / 256, 256>>>(MASK_WORDS);
    set_mask_kernel<<<(B + 255) / 256, 256>>>(ids, B);
    lu_copy_kernel<<<(n_nodes / 4 + 255) / 256, 256>>>(
        (const float4*)last_update, (float4*)out_lu, n_nodes / 4);

    // fork: masked bulk copy of memory on side stream
    cudaEventRecord(e_fork, 0);
    cudaStreamWaitEvent(s_side, e_fork, 0);
    {
        long long n4 = (long long)n_nodes * 32;
        copy_mem_kernel<<<(unsigned)((n4 + 255) / 256), 256, 0, s_side>>>(
            (const float4*)memory, (float4*)out_mem, n_nodes);
    }
    cudaEventRecord(e_join, s_side);

    // main stream: GRU
    int tiles = (B + BLOCK_M - 1) / BLOCK_M;
    gru_update_kernel<<<tiles, THREADS, SMEM_BYTES>>>(
        memory, ids, messages, ts, b_ih, b_hh, out_mem, out_lu, B);

    // join
    cudaStreamWaitEvent(0, e_join, 0);
}

// round 15
// speedup vs baseline: 8.6361x; 1.1575x over previous
#include <cuda_runtime.h>
#include <cuda_fp16.h>
#include <cstdint>

// ============================================================================
// SequenceMemoryUpdater v9 — fused copy + GRU (single kernel), fp16 mma.sync
//
//   stream 0: pack_w -> zero_mask -> set_mask -> lu_copy -> gru_fused
//
// gru_fused (grid = B/64 = 3125, 512 threads):
//   * each CTA ALSO copies its 320-row share of `memory` -> out (mask-skipped);
//     even CTAs copy before their GRU tile, odd CTAs after (chip-wide phase mix)
//   * GRU tile: prolog converts messages + gathered h rows to fp16 smem (1 sync)
//     mainloop: 12 K-chunks, ldmatrix.x4 A-frags, fragment-packed fp16 W via
//     LDG (L2-resident), 24 mma.sync.m16n8k16 per warp per chunk, NO syncs
//   * register-resident GRU epilogue, scatter; h_old re-read fp32 from gmem
// ============================================================================

#define BLOCK_M   64
#define THREADS   512
#define COPY_F4_PER_CTA 10240           // 320 rows x 32 float4

// smem byte offsets
#define OFF_BIAS   0                    // 512 floats = 2048B
#define OFF_IDS    2048                 // 64 ints = 256B
#define OFF_MSG    2304                 // 64 rows x 264 halves = 33792B
#define OFF_HOLD   36096                // 64 rows x 136 halves = 17408B
#define SMEM_BYTES 53504

#define MSG_STRIDE  264                 // halves
#define HOLD_STRIDE 136                 // halves

#define MASK_WORDS 32768                // 1M nodes / 32
__device__ uint32_t g_mask[MASK_WORDS];
// fragment-packed fp16 W: [kc][wq][gate(3)][lane] uint4
__device__ alignas(128) uint4 g_wfrag[12 * 16 * 3 * 32];

// ---- helpers ----
__device__ __forceinline__ uint32_t pack2(float x, float y) {
    __half2 h = __floats2half2_rn(x, y);
    return *(uint32_t*)&h;
}

__device__ __forceinline__ void ldmatrix_x4(uint32_t* a, uint32_t addr) {
    asm volatile(
        "ldmatrix.sync.aligned.m8n8.x4.shared.b16 {%0,%1,%2,%3}, [%4];"
        : "=r"(a[0]), "=r"(a[1]), "=r"(a[2]), "=r"(a[3]) : "r"(addr));
}

__device__ __forceinline__ void mma_f16(float* d, const uint32_t* a,
                                        uint32_t b0, uint32_t b1) {
    asm volatile(
        "mma.sync.aligned.m16n8k16.row.col.f32.f16.f16.f32 "
        "{%0,%1,%2,%3}, {%4,%5,%6,%7}, {%8,%9}, {%0,%1,%2,%3};"
        : "+f"(d[0]), "+f"(d[1]), "+f"(d[2]), "+f"(d[3])
        : "r"(a[0]), "r"(a[1]), "r"(a[2]), "r"(a[3]), "r"(b0), "r"(b1));
}

__device__ __forceinline__ float gru_one(float pr, float pz, float pin,
                                         float phn, float h) {
    float r = 1.0f / (1.0f + __expf(-pr));
    float z = 1.0f / (1.0f + __expf(-pz));
    float n = tanhf(fmaf(r, phn, pin));
    return fmaf(z, h - n, n);   // (1-z)*n + z*h
}

// ---------------------------------------------------------------------------
// W fragment repack (fp16)
// ---------------------------------------------------------------------------
__global__ void pack_w_kernel(const float* __restrict__ W_ih,
                              const float* __restrict__ W_hh) {
    int idx = blockIdx.x * blockDim.x + threadIdx.x;
    if (idx >= 12 * 16 * 3 * 32) return;
    int lane = idx & 31;
    int gate = (idx >> 5) % 3;
    int wq   = (idx >> 5) / 3 % 16;
    int kc   = idx / (32 * 3 * 16);
    const float* W = (kc < 8) ? W_ih : W_hh;
    const int stride = (kc < 8) ? 256 : 128;
    const int col0   = ((kc < 8) ? kc : kc - 8) * 32;
    const int nrow   = gate * 128 + wq * 8 + (lane >> 2);
    uint32_t q[4];
#pragma unroll
    for (int qi = 0; qi < 4; ++qi) {
        int g16 = qi >> 1, r = qi & 1;
        int k = col0 + g16 * 16 + r * 8 + (lane & 3) * 2;
        q[qi] = pack2(W[(size_t)nrow * stride + k],
                      W[(size_t)nrow * stride + k + 1]);
    }
    g_wfrag[idx] = make_uint4(q[0], q[1], q[2], q[3]);
}

// ---------------------------------------------------------------------------
// mask + lu copy
// ---------------------------------------------------------------------------
__global__ void zero_mask_kernel(int n_words) {
    int i = blockIdx.x * blockDim.x + threadIdx.x;
    if (i < n_words) g_mask[i] = 0u;
}
__global__ void set_mask_kernel(const int* __restrict__ ids, int B) {
    int i = blockIdx.x * blockDim.x + threadIdx.x;
    if (i < B) {
        int node = ids[i];
        atomicOr(&g_mask[node >> 5], 1u << (node & 31));
    }
}
__global__ void lu_copy_kernel(const float4* __restrict__ lu,
                               float4* __restrict__ out, int n4) {
    int i = blockIdx.x * blockDim.x + threadIdx.x;
    if (i < n4) out[i] = lu[i];
}

// ---------------------------------------------------------------------------
// per-CTA copy share: 10240 float4s (320 rows), mask-skipped, 4 batches x 5
// ---------------------------------------------------------------------------
__device__ __forceinline__ void copy_span(const float4* __restrict__ mem4,
                                          float4* __restrict__ out4,
                                          long long base, int tid) {
#pragma unroll
    for (int b = 0; b < 4; ++b) {
        long long i[5];
        float4 v[5];
        bool sk[5];
#pragma unroll
        for (int j = 0; j < 5; ++j) {
            i[j] = base + (long long)(b * 5 + j) * THREADS + tid;
            int row = (int)(i[j] >> 5);
            sk[j] = (g_mask[row >> 5] >> (row & 31)) & 1u;
            if (!sk[j]) v[j] = mem4[i[j]];
        }
#pragma unroll
        for (int j = 0; j < 5; ++j)
            if (!sk[j]) out4[i[j]] = v[j];
    }
}

// ---------------------------------------------------------------------------
// fused GRU + copy kernel
// ---------------------------------------------------------------------------
__global__ void __launch_bounds__(THREADS, 1)
gru_fused_kernel(const float* __restrict__ memory,
                 const int*   __restrict__ ids,
                 const float* __restrict__ messages,
                 const float* __restrict__ ts,
                 const float* __restrict__ b_ih,
                 const float* __restrict__ b_hh,
                 float* __restrict__ out_mem,
                 float* __restrict__ out_lu,
                 int B) {
    extern __shared__ char sm[];
    const uint32_t smb = (uint32_t)__cvta_generic_to_shared(sm);
    const int tid  = threadIdx.x;
    const int lane = tid & 31;
    const int wq   = tid >> 5;              // warp = col group
    const int row0 = blockIdx.x * BLOCK_M;

    int* ids_s  = (int*)(sm + OFF_IDS);
    float* bias = (float*)(sm + OFF_BIAS);

    const long long cbase = (long long)blockIdx.x * COPY_F4_PER_CTA;
    const bool copy_first = (blockIdx.x & 1) == 0;

    // ---- even CTAs: copy share first (DRAM phase) ----
    if (copy_first)
        copy_span((const float4*)memory, (float4*)out_mem, cbase, tid);

    // ---- phase 0: ids + fused biases ----
    if (tid < BLOCK_M) {
        int gr = row0 + tid;
        ids_s[tid] = (gr < B) ? ids[gr] : 0;
    }
    {
        float v;
        if (tid < 256)      v = b_ih[tid] + b_hh[tid];      // r,z
        else if (tid < 384) v = b_ih[tid];                  // i_n
        else                v = b_hh[tid - 128];            // h_n
        bias[tid] = v;
    }
    __syncthreads();

    // ---- prolog: load + convert messages and h rows to fp16 smem ----
    {
        int r = tid >> 3, c0 = (tid & 7) * 32;
        int gr = row0 + r; if (gr >= B) gr = B - 1;
        const float4* src = (const float4*)(messages + (size_t)gr * 256 + c0);
        float4 v[8];
#pragma unroll
        for (int j = 0; j < 8; ++j) v[j] = src[j];
        uint4* dst = (uint4*)(sm + OFF_MSG + (r * MSG_STRIDE + c0) * 2);
#pragma unroll
        for (int j = 0; j < 4; ++j)
            dst[j] = make_uint4(pack2(v[2*j].x,   v[2*j].y),
                                pack2(v[2*j].z,   v[2*j].w),
                                pack2(v[2*j+1].x, v[2*j+1].y),
                                pack2(v[2*j+1].z, v[2*j+1].w));
        int hc0 = (tid & 7) * 16;
        const float4* hs = (const float4*)(memory +
                               (size_t)ids_s[r] * 128 + hc0);
        float4 hv[4];
#pragma unroll
        for (int j = 0; j < 4; ++j) hv[j] = hs[j];
        uint4* hd = (uint4*)(sm + OFF_HOLD + (r * HOLD_STRIDE + hc0) * 2);
#pragma unroll
        for (int j = 0; j < 2; ++j)
            hd[j] = make_uint4(pack2(hv[2*j].x,   hv[2*j].y),
                               pack2(hv[2*j].z,   hv[2*j].w),
                               pack2(hv[2*j+1].x, hv[2*j+1].y),
                               pack2(hv[2*j+1].z, hv[2*j+1].w));
    }
    __syncthreads();    // the ONLY mainloop-relevant barrier

    float acc[4][4][4];                      // [mt][gate r/z/in/hn][c]
#pragma unroll
    for (int mt = 0; mt < 4; ++mt)
#pragma unroll
        for (int g = 0; g < 4; ++g)
#pragma unroll
            for (int c = 0; c < 4; ++c) acc[mt][g][c] = 0.0f;

    const uint4* wbase = g_wfrag + (size_t)wq * 3 * 32 + lane;
    const int lm_row = lane & 15;
    const int lm_seg = (lane >> 4) * 8;      // halves

    // ---- mainloop: 12 chunks, no syncs ----
#pragma unroll
    for (int kc = 0; kc < 12; ++kc) {
        uint4 wv[3];
        const uint4* wf = wbase + (size_t)kc * 16 * 3 * 32;
        wv[0] = wf[0]; wv[1] = wf[32]; wv[2] = wf[64];

        uint32_t abase;
        if (kc < 8)
            abase = smb + OFF_MSG +
                    (lm_row * MSG_STRIDE + kc * 32 + lm_seg) * 2;
        else
            abase = smb + OFF_HOLD +
                    (lm_row * HOLD_STRIDE + (kc - 8) * 32 + lm_seg) * 2;
        const int astride = (kc < 8) ? MSG_STRIDE : HOLD_STRIDE;
        const int G2 = (kc < 8) ? 2 : 3;

#pragma unroll
        for (int g16 = 0; g16 < 2; ++g16) {
            uint32_t a[4][4];
#pragma unroll
            for (int mt = 0; mt < 4; ++mt)
                ldmatrix_x4(a[mt], abase + (mt * 16 * astride + g16 * 16) * 2);
#pragma unroll
            for (int gate = 0; gate < 3; ++gate) {
                const int gi = (gate == 2) ? G2 : gate;
                uint32_t b0 = g16 ? wv[gate].z : wv[gate].x;
                uint32_t b1 = g16 ? wv[gate].w : wv[gate].y;
#pragma unroll
                for (int mt = 0; mt < 4; ++mt)
                    mma_f16(acc[mt][gi], a[mt], b0, b1);
            }
        }
    }

    // ---- register-resident GRU epilogue + scatter ----
#pragma unroll
    for (int mt = 0; mt < 4; ++mt) {
#pragma unroll
        for (int half = 0; half < 2; ++half) {     // acc c{0,1} vs c{2,3}
            int row_l = mt * 16 + (lane >> 2) + half * 8;
            int gr = row0 + row_l;
            int node = ids_s[row_l];
            float* orow = out_mem + (size_t)node * 128;
            const int c0 = half * 2;
            int hc = wq * 8 + (lane & 3) * 2;
            float2 ho = *(const float2*)(memory + (size_t)node * 128 + hc);
            float2 br = *(const float2*)(bias + hc);
            float2 bz = *(const float2*)(bias + 128 + hc);
            float2 bi = *(const float2*)(bias + 256 + hc);
            float2 bh = *(const float2*)(bias + 384 + hc);
            float2 res;
            res.x = gru_one(acc[mt][0][c0]     + br.x,
                            acc[mt][1][c0]     + bz.x,
                            acc[mt][2][c0]     + bi.x,
                            acc[mt][3][c0]     + bh.x, ho.x);
            res.y = gru_one(acc[mt][0][c0 + 1] + br.y,
                            acc[mt][1][c0 + 1] + bz.y,
                            acc[mt][2][c0 + 1] + bi.y,
                            acc[mt][3][c0 + 1] + bh.y, ho.y);
            if (gr < B) *(float2*)(orow + hc) = res;
        }
    }
    if (tid < BLOCK_M) {
        int gr = row0 + tid;
        if (gr < B) out_lu[ids_s[tid]] = ts[gr];
    }

    // ---- odd CTAs: copy share last (DRAM phase) ----
    if (!copy_first)
        copy_span((const float4*)memory, (float4*)out_mem, cbase, tid);
}

// ---------------------------------------------------------------------------
extern "C" void kernel_launch(void* const* d_in, const int* in_sizes, int n_in,
                              void* d_out, int out_size) {
    const float* memory      = (const float*)d_in[0];
    const float* last_update = (const float*)d_in[1];
    const int*   ids         = (const int*)d_in[2];
    const float* messages    = (const float*)d_in[3];
    const float* ts          = (const float*)d_in[4];
    const float* W_ih        = (const float*)d_in[5];
    const float* W_hh        = (const float*)d_in[6];
    const float* b_ih        = (const float*)d_in[7];
    const float* b_hh        = (const float*)d_in[8];

    const int n_nodes = in_sizes[1];
    const int B       = in_sizes[2];

    float* out_mem = (float*)d_out;
    float* out_lu  = out_mem + (size_t)n_nodes * 128;

    static bool inited = false;
    if (!inited) {
        cudaFuncSetAttribute(gru_fused_kernel,
                             cudaFuncAttributeMaxDynamicSharedMemorySize,
                             SMEM_BYTES);
        inited = true;
    }

    pack_w_kernel<<<(12 * 16 * 3 * 32 + 255) / 256, 256>>>(W_ih, W_hh);
    zero_mask_kernel<<<(MASK_WORDS + 255) / 256, 256>>>(MASK_WORDS);
    set_mask_kernel<<<(B + 255) / 256, 256>>>(ids, B);
    lu_copy_kernel<<<(n_nodes / 4 + 255) / 256, 256>>>(
        (const float4*)last_update, (float4*)out_lu, n_nodes / 4);

    int tiles = (B + BLOCK_M - 1) / BLOCK_M;
    gru_fused_kernel<<<tiles, THREADS, SMEM_BYTES>>>(
        memory, ids, messages, ts, b_ih, b_hh, out_mem, out_lu, B);
}

// round 16
// speedup vs baseline: 8.6657x; 1.0034x over previous
#include <cuda_runtime.h>
#include <cuda_fp16.h>
#include <cstdint>

// ============================================================================
// SequenceMemoryUpdater v10 — copy software-pipelined INSIDE the MMA mainloop
//
//   stream 0: pack_w -> zero_mask -> set_mask -> lu_copy -> gru_fused
//
// gru_fused (grid = B/64 = 3125, 512 threads, 1 CTA/SM):
//   * per-thread copy share = 20 float4 of `memory`->out (mask-skipped),
//     pipelined 2 slots/chunk between MMA half-chunks (load leads store by
//     one chunk -> DRAM latency hidden under tensor work)
//   * GRU tile: prolog converts messages + gathered h rows to fp16 smem AND
//     keeps an fp32 h copy in smem for the epilogue (1 sync)
//   * mainloop: 12 K-chunks, ldmatrix.x4 A-frags, fragment-packed fp16 W via
//     LDG (L2-resident), 24 mma.sync.m16n8k16 per warp per chunk, NO syncs
//   * register-resident GRU epilogue (h_old fp32 from smem), scatter
// ============================================================================

#define BLOCK_M   64
#define THREADS   512
#define COPY_SLOTS 20                   // 20 x 512 float4 = 10240 f4/CTA

// smem byte offsets
#define OFF_BIAS   0                    // 512 floats = 2048B
#define OFF_IDS    2048                 // 64 ints = 256B
#define OFF_MSG    2304                 // 64 rows x 264 halves = 33792B
#define OFF_HOLD   36096                // 64 rows x 136 halves = 17408B
#define OFF_H32    53504                // 64 rows x 132 floats = 33792B
#define SMEM_BYTES 87296

#define MSG_STRIDE  264                 // halves
#define HOLD_STRIDE 136                 // halves
#define H32_STRIDE  132                 // floats

#define MASK_WORDS 32768                // 1M nodes / 32
__device__ uint32_t g_mask[MASK_WORDS];
// fragment-packed fp16 W: [kc][wq][gate(3)][lane] uint4
__device__ alignas(128) uint4 g_wfrag[12 * 16 * 3 * 32];

// ---- helpers ----
__device__ __forceinline__ uint32_t pack2(float x, float y) {
    __half2 h = __floats2half2_rn(x, y);
    return *(uint32_t*)&h;
}

__device__ __forceinline__ void ldmatrix_x4(uint32_t* a, uint32_t addr) {
    asm volatile(
        "ldmatrix.sync.aligned.m8n8.x4.shared.b16 {%0,%1,%2,%3}, [%4];"
        : "=r"(a[0]), "=r"(a[1]), "=r"(a[2]), "=r"(a[3]) : "r"(addr));
}

__device__ __forceinline__ void mma_f16(float* d, const uint32_t* a,
                                        uint32_t b0, uint32_t b1) {
    asm volatile(
        "mma.sync.aligned.m16n8k16.row.col.f32.f16.f16.f32 "
        "{%0,%1,%2,%3}, {%4,%5,%6,%7}, {%8,%9}, {%0,%1,%2,%3};"
        : "+f"(d[0]), "+f"(d[1]), "+f"(d[2]), "+f"(d[3])
        : "r"(a[0]), "r"(a[1]), "r"(a[2]), "r"(a[3]), "r"(b0), "r"(b1));
}

__device__ __forceinline__ float gru_one(float pr, float pz, float pin,
                                         float phn, float h) {
    float r = 1.0f / (1.0f + __expf(-pr));
    float z = 1.0f / (1.0f + __expf(-pz));
    float n = tanhf(fmaf(r, phn, pin));
    return fmaf(z, h - n, n);   // (1-z)*n + z*h
}

// ---------------------------------------------------------------------------
// W fragment repack (fp16)
// ---------------------------------------------------------------------------
__global__ void pack_w_kernel(const float* __restrict__ W_ih,
                              const float* __restrict__ W_hh) {
    int idx = blockIdx.x * blockDim.x + threadIdx.x;
    if (idx >= 12 * 16 * 3 * 32) return;
    int lane = idx & 31;
    int gate = (idx >> 5) % 3;
    int wq   = (idx >> 5) / 3 % 16;
    int kc   = idx / (32 * 3 * 16);
    const float* W = (kc < 8) ? W_ih : W_hh;
    const int stride = (kc < 8) ? 256 : 128;
    const int col0   = ((kc < 8) ? kc : kc - 8) * 32;
    const int nrow   = gate * 128 + wq * 8 + (lane >> 2);
    uint32_t q[4];
#pragma unroll
    for (int qi = 0; qi < 4; ++qi) {
        int g16 = qi >> 1, r = qi & 1;
        int k = col0 + g16 * 16 + r * 8 + (lane & 3) * 2;
        q[qi] = pack2(W[(size_t)nrow * stride + k],
                      W[(size_t)nrow * stride + k + 1]);
    }
    g_wfrag[idx] = make_uint4(q[0], q[1], q[2], q[3]);
}

// ---------------------------------------------------------------------------
// mask + lu copy
// ---------------------------------------------------------------------------
__global__ void zero_mask_kernel(int n_words) {
    int i = blockIdx.x * blockDim.x + threadIdx.x;
    if (i < n_words) g_mask[i] = 0u;
}
__global__ void set_mask_kernel(const int* __restrict__ ids, int B) {
    int i = blockIdx.x * blockDim.x + threadIdx.x;
    if (i < B) {
        int node = ids[i];
        atomicOr(&g_mask[node >> 5], 1u << (node & 31));
    }
}
__global__ void lu_copy_kernel(const float4* __restrict__ lu,
                               float4* __restrict__ out, int n4) {
    int i = blockIdx.x * blockDim.x + threadIdx.x;
    if (i < n4) out[i] = lu[i];
}

// ---------------------------------------------------------------------------
// fused GRU + pipelined-copy kernel
// ---------------------------------------------------------------------------
__global__ void __launch_bounds__(THREADS, 1)
gru_fused_kernel(const float* __restrict__ memory,
                 const int*   __restrict__ ids,
                 const float* __restrict__ messages,
                 const float* __restrict__ ts,
                 const float* __restrict__ b_ih,
                 const float* __restrict__ b_hh,
                 float* __restrict__ out_mem,
                 float* __restrict__ out_lu,
                 int B) {
    extern __shared__ char sm[];
    const uint32_t smb = (uint32_t)__cvta_generic_to_shared(sm);
    const int tid  = threadIdx.x;
    const int lane = tid & 31;
    const int wq   = tid >> 5;              // warp = col group
    const int row0 = blockIdx.x * BLOCK_M;

    int* ids_s   = (int*)(sm + OFF_IDS);
    float* bias  = (float*)(sm + OFF_BIAS);
    float* h32   = (float*)(sm + OFF_H32);

    const float4* mem4 = (const float4*)memory;
    float4* out4 = (float4*)out_mem;
    // per-thread copy base (float4 index); COPY_SLOTS*THREADS per CTA
    const int cbase = blockIdx.x * (COPY_SLOTS * THREADS) + tid;

    // ---- phase 0: ids + fused biases ----
    if (tid < BLOCK_M) {
        int gr = row0 + tid;
        ids_s[tid] = (gr < B) ? ids[gr] : 0;
    }
    {
        float v;
        if (tid < 256)      v = b_ih[tid] + b_hh[tid];      // r,z
        else if (tid < 384) v = b_ih[tid];                  // i_n
        else                v = b_hh[tid - 128];            // h_n
        bias[tid] = v;
    }
    __syncthreads();

    // ---- prolog: messages + h rows -> fp16 smem; h rows also -> fp32 smem ----
    {
        int r = tid >> 3, c0 = (tid & 7) * 32;
        int gr = row0 + r; if (gr >= B) gr = B - 1;
        const float4* src = (const float4*)(messages + (size_t)gr * 256 + c0);
        float4 v[8];
#pragma unroll
        for (int j = 0; j < 8; ++j) v[j] = src[j];
        uint4* dst = (uint4*)(sm + OFF_MSG + (r * MSG_STRIDE + c0) * 2);
#pragma unroll
        for (int j = 0; j < 4; ++j)
            dst[j] = make_uint4(pack2(v[2*j].x,   v[2*j].y),
                                pack2(v[2*j].z,   v[2*j].w),
                                pack2(v[2*j+1].x, v[2*j+1].y),
                                pack2(v[2*j+1].z, v[2*j+1].w));
        int hc0 = (tid & 7) * 16;
        const float4* hs = (const float4*)(memory +
                               (size_t)ids_s[r] * 128 + hc0);
        float4 hv[4];
#pragma unroll
        for (int j = 0; j < 4; ++j) hv[j] = hs[j];
        uint4* hd = (uint4*)(sm + OFF_HOLD + (r * HOLD_STRIDE + hc0) * 2);
#pragma unroll
        for (int j = 0; j < 2; ++j)
            hd[j] = make_uint4(pack2(hv[2*j].x,   hv[2*j].y),
                               pack2(hv[2*j].z,   hv[2*j].w),
                               pack2(hv[2*j+1].x, hv[2*j+1].y),
                               pack2(hv[2*j+1].z, hv[2*j+1].w));
        float4* h32d = (float4*)(h32 + r * H32_STRIDE + hc0);
#pragma unroll
        for (int j = 0; j < 4; ++j) h32d[j] = hv[j];
    }
    __syncthreads();    // the ONLY mainloop-relevant barrier

    float acc[4][4][4];                      // [mt][gate r/z/in/hn][c]
#pragma unroll
    for (int mt = 0; mt < 4; ++mt)
#pragma unroll
        for (int g = 0; g < 4; ++g)
#pragma unroll
            for (int c = 0; c < 4; ++c) acc[mt][g][c] = 0.0f;

    const uint4* wbase = g_wfrag + (size_t)wq * 3 * 32 + lane;
    const int lm_row = lane & 15;
    const int lm_seg = (lane >> 4) * 8;      // halves

    // ---- copy pipeline state: 2 slots in flight ----
    float4 cv[2];
    int ci[2];
    bool cs[2];
#pragma unroll
    for (int b = 0; b < 2; ++b) {
        ci[b] = cbase + b * THREADS;
        int row = ci[b] >> 5;
        cs[b] = (g_mask[row >> 5] >> (row & 31)) & 1u;
        if (!cs[b]) cv[b] = mem4[ci[b]];
    }

    // ---- mainloop: 12 chunks, no syncs; copy interleaved 2 slots/chunk ----
#pragma unroll
    for (int kc = 0; kc < 12; ++kc) {
        uint4 wv[3];
        const uint4* wf = wbase + (size_t)kc * 16 * 3 * 32;
        wv[0] = wf[0]; wv[1] = wf[32]; wv[2] = wf[64];

        uint32_t abase;
        if (kc < 8)
            abase = smb + OFF_MSG +
                    (lm_row * MSG_STRIDE + kc * 32 + lm_seg) * 2;
        else
            abase = smb + OFF_HOLD +
                    (lm_row * HOLD_STRIDE + (kc - 8) * 32 + lm_seg) * 2;
        const int astride = (kc < 8) ? MSG_STRIDE : HOLD_STRIDE;
        const int G2 = (kc < 8) ? 2 : 3;

#pragma unroll
        for (int g16 = 0; g16 < 2; ++g16) {
            uint32_t a[4][4];
#pragma unroll
            for (int mt = 0; mt < 4; ++mt)
                ldmatrix_x4(a[mt], abase + (mt * 16 * astride + g16 * 16) * 2);
#pragma unroll
            for (int gate = 0; gate < 3; ++gate) {
                const int gi = (gate == 2) ? G2 : gate;
                uint32_t b0 = g16 ? wv[gate].z : wv[gate].x;
                uint32_t b1 = g16 ? wv[gate].w : wv[gate].y;
#pragma unroll
                for (int mt = 0; mt < 4; ++mt)
                    mma_f16(acc[mt][gi], a[mt], b0, b1);
            }
            // copy step: store slot (2*kc+g16), load slot (2*kc+g16+2)
            {
                const int s_next = 2 * kc + g16 + 2;
                if (!cs[g16]) out4[ci[g16]] = cv[g16];
                if (s_next < COPY_SLOTS) {
                    ci[g16] = cbase + s_next * THREADS;
                    int row = ci[g16] >> 5;
                    cs[g16] = (g_mask[row >> 5] >> (row & 31)) & 1u;
                    if (!cs[g16]) cv[g16] = mem4[ci[g16]];
                } else {
                    cs[g16] = true;
                }
            }
        }
    }

    // ---- register-resident GRU epilogue + scatter (h_old fp32 from smem) ----
#pragma unroll
    for (int mt = 0; mt < 4; ++mt) {
#pragma unroll
        for (int half = 0; half < 2; ++half) {     // acc c{0,1} vs c{2,3}
            int row_l = mt * 16 + (lane >> 2) + half * 8;
            int gr = row0 + row_l;
            int node = ids_s[row_l];
            float* orow = out_mem + (size_t)node * 128;
            const int c0 = half * 2;
            int hc = wq * 8 + (lane & 3) * 2;
            float2 ho = *(const float2*)(h32 + row_l * H32_STRIDE + hc);
            float2 br = *(const float2*)(bias + hc);
            float2 bz = *(const float2*)(bias + 128 + hc);
            float2 bi = *(const float2*)(bias + 256 + hc);
            float2 bh = *(const float2*)(bias + 384 + hc);
            float2 res;
            res.x = gru_one(acc[mt][0][c0]     + br.x,
                            acc[mt][1][c0]     + bz.x,
                            acc[mt][2][c0]     + bi.x,
                            acc[mt][3][c0]     + bh.x, ho.x);
            res.y = gru_one(acc[mt][0][c0 + 1] + br.y,
                            acc[mt][1][c0 + 1] + bz.y,
                            acc[mt][2][c0 + 1] + bi.y,
                            acc[mt][3][c0 + 1] + bh.y, ho.y);
            if (gr < B) *(float2*)(orow + hc) = res;
        }
    }
    if (tid < BLOCK_M) {
        int gr = row0 + tid;
        if (gr < B) out_lu[ids_s[tid]] = ts[gr];
    }
}

// ---------------------------------------------------------------------------
extern "C" void kernel_launch(void* const* d_in, const int* in_sizes, int n_in,
                              void* d_out, int out_size) {
    const float* memory      = (const float*)d_in[0];
    const float* last_update = (const float*)d_in[1];
    const int*   ids         = (const int*)d_in[2];
    const float* messages    = (const float*)d_in[3];
    const float* ts          = (const float*)d_in[4];
    const float* W_ih        = (const float*)d_in[5];
    const float* W_hh        = (const float*)d_in[6];
    const float* b_ih        = (const float*)d_in[7];
    const float* b_hh        = (const float*)d_in[8];

    const int n_nodes = in_sizes[1];
    const int B       = in_sizes[2];

    float* out_mem = (float*)d_out;
    float* out_lu  = out_mem + (size_t)n_nodes * 128;

    static bool inited = false;
    if (!inited) {
        cudaFuncSetAttribute(gru_fused_kernel,
                             cudaFuncAttributeMaxDynamicSharedMemorySize,
                             SMEM_BYTES);
        inited = true;
    }

    pack_w_kernel<<<(12 * 16 * 3 * 32 + 255) / 256, 256>>>(W_ih, W_hh);
    zero_mask_kernel<<<(MASK_WORDS + 255) / 256, 256>>>(MASK_WORDS);
    set_mask_kernel<<<(B + 255) / 256, 256>>>(ids, B);
    lu_copy_kernel<<<(n_nodes / 4 + 255) / 256, 256>>>(
        (const float4*)last_update, (float4*)out_lu, n_nodes / 4);

    int tiles = (B + BLOCK_M - 1) / BLOCK_M;
    gru_fused_kernel<<<tiles, THREADS, SMEM_BYTES>>>(
        memory, ids, messages, ts, b_ih, b_hh, out_mem, out_lu, B);
}